// round 8
// baseline (speedup 1.0000x reference)
#include <cuda_runtime.h>
#include <math_constants.h>

// Fixed problem shape: x[B=4, C=256, H=200, W=320] float32 -> out[B, H, W] float32
#define Bn 4
#define Cn 256
#define Hn 200
#define Wn 320
#define HWn (Hn * Wn)            // 64000
#define NPIX (Bn * HWn)          // 256000

#define NCH 8                    // channel chunks
#define CPC (Cn / NCH)           // 32 channels per chunk
#define TH  8                    // output rows per strip
#define NSY (Hn / TH)            // 25 strips
#define GW  (Wn / 4)             // 80 float4 column groups

#define N_INTERIOR (NCH * Bn * NSY * (GW - 2))  // 62400
#define N_TOTAL    (NCH * Bn * NSY * GW)        // 64000
#define TPB 128

#define NEG_INF (-CUDART_INF_F)

// Per-chunk partials: max and passing-count (count of channels in chunk with
// v == chunkmax && 9x9-windowmax == v).
__device__ float g_pm[NCH * NPIX];   // 8 MB
__device__ float g_pc[NCH * NPIX];   // 8 MB

__device__ __forceinline__ float4 f4max(float4 a, float4 b) {
    return make_float4(fmaxf(a.x, b.x), fmaxf(a.y, b.y),
                       fmaxf(a.z, b.z), fmaxf(a.w, b.w));
}

// Running (depth-max, passing-count) update for one pixel/channel.
// wm >= v always (window includes center), so pass <=> wm == v.
__device__ __forceinline__ void upd(float& m, float& n, float v, float wm) {
    const bool pass = (wm <= v);
    const bool gt = v > m;
    const bool eq = v == m;
    n = gt ? (pass ? 1.f : 0.f) : (n + ((eq && pass) ? 1.f : 0.f));
    m = fmaxf(m, v);
}

// One thread: one channel chunk x one 8-row full-height strip x 4 columns.
// Streams CPC channels; per channel does separable 9x9 windowmax on the fly.
template <bool EDGE>
__device__ __forceinline__ void run_strip(const float* __restrict__ x,
                                          int chunk, int b, int y0, int gx) {
    const int X = gx * 4;
    int wa = X - 4;
    if (wa < 0) wa = 0;
    if (wa > Wn - 12) wa = Wn - 12;       // 308, 16B-aligned
    const int off = (X - 4) - wa;         // 0 interior, -4 left edge, +4 right edge

    float4 mx[TH], cnt[TH];
#pragma unroll
    for (int j = 0; j < TH; ++j) {
        mx[j]  = make_float4(NEG_INF, NEG_INF, NEG_INF, NEG_INF);
        cnt[j] = make_float4(0.f, 0.f, 0.f, 0.f);
    }

    const float* plane = x + (size_t)(b * Cn + chunk * CPC) * HWn;

    for (int c = 0; c < CPC; ++c, plane += HWn) {
        float4 ring[9];                   // last 9 horizontal-max rows
#pragma unroll
        for (int i = 0; i < TH + 8; ++i) {
            int ly = y0 - 4 + i;
            ly = ly < 0 ? 0 : (ly > Hn - 1 ? Hn - 1 : ly);   // clamp dup: max-safe
            const float4* rp =
                reinterpret_cast<const float4*>(plane + ly * Wn + wa);
            const float4 a  = __ldg(rp + 0);
            const float4 bb = __ldg(rp + 1);
            const float4 cc = __ldg(rp + 2);

            float4 hm;
            if (!EDGE) {
                // span v0..v11 = a|bb|cc; window for out col X+k = local j in [k, k+8]
                const float core = fmaxf(fmaxf(fmaxf(a.w, bb.x), fmaxf(bb.y, bb.z)),
                                         fmaxf(bb.w, cc.x));       // j3..8
                const float p12  = fmaxf(a.y, a.z);                // v1,v2
                const float p910 = fmaxf(cc.y, cc.z);              // v9,v10
                hm.x = fmaxf(fmaxf(core, a.x),  p12);
                hm.y = fmaxf(fmaxf(core, cc.y), p12);
                hm.z = fmaxf(fmaxf(core, a.z),  p910);
                hm.w = fmaxf(fmaxf(core, cc.w), p910);
            } else {
                const float vv[12] = {a.x, a.y, a.z, a.w, bb.x, bb.y, bb.z, bb.w,
                                      cc.x, cc.y, cc.z, cc.w};
                float m[4];
#pragma unroll
                for (int k = 0; k < 4; ++k) {
                    m[k] = NEG_INF;
#pragma unroll
                    for (int j = 0; j < 12; ++j)
                        if (j >= k + off && j <= k + 8 + off)
                            m[k] = fmaxf(m[k], vv[j]);
                }
                hm = make_float4(m[0], m[1], m[2], m[3]);
            }
            ring[i % 9] = hm;

            if (i >= 8) {
                const int j = i - 8;      // output row within strip
                float4 vm = f4max(f4max(f4max(ring[0], ring[1]),
                                        f4max(ring[2], ring[3])),
                                  f4max(f4max(ring[4], ring[5]),
                                        f4max(ring[6], ring[7])));
                vm = f4max(vm, ring[8]);  // full 9x9 window max
                const float4 v = __ldg(
                    reinterpret_cast<const float4*>(plane + (y0 + j) * Wn + X));
                upd(mx[j].x, cnt[j].x, v.x, vm.x);
                upd(mx[j].y, cnt[j].y, v.y, vm.y);
                upd(mx[j].z, cnt[j].z, v.z, vm.z);
                upd(mx[j].w, cnt[j].w, v.w, vm.w);
            }
        }
    }

    const size_t base = (size_t)chunk * NPIX + (size_t)b * HWn;
#pragma unroll
    for (int j = 0; j < TH; ++j) {
        const size_t idx = base + (size_t)(y0 + j) * Wn + X;
        *reinterpret_cast<float4*>(&g_pm[idx]) = mx[j];
        *reinterpret_cast<float4*>(&g_pc[idx]) = cnt[j];
    }
}

__global__ void __launch_bounds__(TPB)
fused_kernel(const float* __restrict__ x) {
    const int tg = blockIdx.x * TPB + threadIdx.x;   // 0..N_TOTAL-1 exact
    if (tg < N_INTERIOR) {
        // Interior columns gx=1..78: warps are uniformly interior
        // (N_INTERIOR = 62400 is a multiple of 32).
        const int gx = 1 + tg % (GW - 2);
        const int s  = tg / (GW - 2);
        const int chunk = s / (Bn * NSY);
        const int rem   = s % (Bn * NSY);
        run_strip<false>(x, chunk, rem / NSY, (rem % NSY) * TH, gx);
    } else {
        // Edge columns gx=0 and gx=79 packed into dedicated warps.
        const int e  = tg - N_INTERIOR;
        const int gx = (e & 1) ? (GW - 1) : 0;
        const int s  = e >> 1;
        const int chunk = s / (Bn * NSY);
        const int rem   = s % (Bn * NSY);
        run_strip<true>(x, chunk, rem / NSY, (rem % NSY) * TH, gx);
    }
}

// Merge the NCH chunk partials per pixel: global max, sum counts of chunks
// achieving it; output = mx * cnt (exactly the reference sum).
__global__ void __launch_bounds__(256)
merge_kernel(float* __restrict__ out) {
    const int p4 = blockIdx.x * 256 + threadIdx.x;   // 0..NPIX/4-1 exact
    float4 mx = make_float4(NEG_INF, NEG_INF, NEG_INF, NEG_INF);
    float4 ct = make_float4(0.f, 0.f, 0.f, 0.f);
#pragma unroll
    for (int ch = 0; ch < NCH; ++ch) {
        const float4 m = *reinterpret_cast<const float4*>(
            &g_pm[(size_t)ch * NPIX + (size_t)p4 * 4]);
        const float4 c = *reinterpret_cast<const float4*>(
            &g_pc[(size_t)ch * NPIX + (size_t)p4 * 4]);
        {   bool gt = m.x > mx.x, eq = m.x == mx.x;
            ct.x = gt ? c.x : (ct.x + (eq ? c.x : 0.f)); mx.x = fmaxf(mx.x, m.x); }
        {   bool gt = m.y > mx.y, eq = m.y == mx.y;
            ct.y = gt ? c.y : (ct.y + (eq ? c.y : 0.f)); mx.y = fmaxf(mx.y, m.y); }
        {   bool gt = m.z > mx.z, eq = m.z == mx.z;
            ct.z = gt ? c.z : (ct.z + (eq ? c.z : 0.f)); mx.z = fmaxf(mx.z, m.z); }
        {   bool gt = m.w > mx.w, eq = m.w == mx.w;
            ct.w = gt ? c.w : (ct.w + (eq ? c.w : 0.f)); mx.w = fmaxf(mx.w, m.w); }
    }
    reinterpret_cast<float4*>(out)[p4] =
        make_float4(mx.x * ct.x, mx.y * ct.y, mx.z * ct.z, mx.w * ct.w);
}

extern "C" void kernel_launch(void* const* d_in, const int* in_sizes, int n_in,
                              void* d_out, int out_size) {
    const float* x = (const float*)d_in[0];
    float* out = (float*)d_out;
    (void)in_sizes; (void)n_in; (void)out_size;

    fused_kernel<<<N_TOTAL / TPB, TPB>>>(x);        // 500 blocks
    merge_kernel<<<(NPIX / 4) / 256, 256>>>(out);   // 250 blocks
}

// round 9
// speedup vs baseline: 1.5415x; 1.5415x over previous
#include <cuda_runtime.h>
#include <math_constants.h>

// x[B=4, C=256, H=200, W=320] f32 -> out[B,H,W] f32
#define Bn 4
#define Cn 256
#define Hn 200
#define Wn 320
#define HWn (Hn * Wn)        // 64000
#define HW4 (HWn / 4)        // 16000 float4/plane
#define NPIX (Bn * HWn)      // 256000
#define GW (Wn / 4)          // 80 groups/row
#define LANES 96             // 3 warps cover GW (16 idle lanes)

#define NEG_INF (-CUDART_INF_F)

__device__ float4 g_pD[4 * Bn * HW4];   // 4 MB: per-chunk partial depth max
__device__ float  g_D[NPIX];            // 1 MB: depthwise max

__device__ __forceinline__ float4 f4max(float4 a, float4 b) {
    return make_float4(fmaxf(a.x, b.x), fmaxf(a.y, b.y),
                       fmaxf(a.z, b.z), fmaxf(a.w, b.w));
}

// ---- K1a: partial depthwise max over 64-channel chunk (pure fmax) ----------
__global__ void __launch_bounds__(256)
dmax_partial_kernel(const float* __restrict__ x) {
    const int g = blockIdx.x * 256 + threadIdx.x;   // 0..Bn*HW4-1 exact
    const int chunk = blockIdx.y;                   // 0..3
    const int b  = g / HW4;
    const int pg = g - b * HW4;

    const float4* __restrict__ src = reinterpret_cast<const float4*>(x)
        + (size_t)(b * Cn + chunk * 64) * HW4 + pg;

    float4 a0 = make_float4(NEG_INF, NEG_INF, NEG_INF, NEG_INF);
    float4 a1 = a0, a2 = a0, a3 = a0;
#pragma unroll 4
    for (int c = 0; c < 64; c += 16) {
        float4 v[16];
#pragma unroll
        for (int j = 0; j < 16; ++j) v[j] = __ldg(src + (size_t)(c + j) * HW4);
#pragma unroll
        for (int j = 0; j < 16; j += 4) {
            a0 = f4max(a0, v[j + 0]);
            a1 = f4max(a1, v[j + 1]);
            a2 = f4max(a2, v[j + 2]);
            a3 = f4max(a3, v[j + 3]);
        }
    }
    g_pD[(size_t)chunk * (Bn * HW4) + g] = f4max(f4max(a0, a1), f4max(a2, a3));
}

// ---- K1b: merge 4 partials -> g_D; zero the output ------------------------
__global__ void __launch_bounds__(256)
dmax_merge_kernel(float* __restrict__ out) {
    const int g = blockIdx.x * 256 + threadIdx.x;   // 0..Bn*HW4-1 exact
    float4 m = f4max(f4max(g_pD[g], g_pD[Bn * HW4 + g]),
                     f4max(g_pD[2 * Bn * HW4 + g], g_pD[3 * Bn * HW4 + g]));
    reinterpret_cast<float4*>(g_D)[g] = m;
    reinterpret_cast<float4*>(out)[g] = make_float4(0.f, 0.f, 0.f, 0.f);
}

// ---- K2: per-(b,c) dense separable 9x9 windowmax sweep + atomic emit -------
// Block = one (b, c) plane; 96 threads = 3 warps covering 80 float4 groups.
// Each thread sweeps all rows (no vertical re-read); horizontal halo via shfl,
// warp-edge lanes fetch one halo float4 from gmem (L1/L2 hit).
__global__ void __launch_bounds__(LANES)
sweep_kernel(const float* __restrict__ x, float* __restrict__ out) {
    const int gx   = threadIdx.x;          // float4 group 0..95 (80..95 idle)
    const int lane = threadIdx.x & 31;
    const int c = blockIdx.x & (Cn - 1);
    const int b = blockIdx.x >> 8;

    const float4* __restrict__ plane4 =
        reinterpret_cast<const float4*>(x) + (size_t)(b * Cn + c) * HW4;
    const float4* __restrict__ d4 =
        reinterpret_cast<const float4*>(g_D) + (size_t)b * HW4;

    const bool active = gx < GW;
    const bool lhalo = (lane == 0)  && (gx != 0) && active;  // gx 32, 64
    const bool rhalo = (lane == 31) && (gx < GW - 1);        // gx 31, 63

    const float4 NEG4 = make_float4(NEG_INF, NEG_INF, NEG_INF, NEG_INF);
    float4 vr[8], hmr[2], pr[4], qd[8], oc[2];
#pragma unroll
    for (int i = 0; i < 8; ++i) { vr[i] = NEG4; qd[i] = NEG4; }
    hmr[0] = hmr[1] = NEG4; oc[0] = oc[1] = NEG4;
    pr[0] = pr[1] = pr[2] = pr[3] = NEG4;

    for (int it = 0; it < 26; ++it) {
#pragma unroll
        for (int u = 0; u < 8; ++u) {
            const int r = it * 8 + u - 4;
            const int ly = min(max(r, 0), Hn - 1);   // clamp dup: max-safe
            const float4* rowp = plane4 + ly * GW;

            const float4 va = active ? __ldg(rowp + gx) : NEG4;
            const float4 hl = lhalo ? __ldg(rowp + gx - 1) : NEG4;
            const float4 hr = rhalo ? __ldg(rowp + gx + 1) : NEG4;
            vr[u & 7] = va;

            // prefix p0..p3 / suffix s0..s3 of own 4 cols (s0 == p3)
            const float p1 = fmaxf(va.x, va.y);
            const float p2 = fmaxf(p1, va.z);
            const float p3 = fmaxf(p2, va.w);
            const float s2 = fmaxf(va.z, va.w);
            const float s1 = fmaxf(va.y, s2);

            // neighbor arrays via shfl
            float ls0 = __shfl_up_sync(0xFFFFFFFFu, p3, 1);
            float ls1 = __shfl_up_sync(0xFFFFFFFFu, s1, 1);
            float ls2 = __shfl_up_sync(0xFFFFFFFFu, s2, 1);
            float ls3 = __shfl_up_sync(0xFFFFFFFFu, va.w, 1);
            float rp0 = __shfl_down_sync(0xFFFFFFFFu, va.x, 1);
            float rp1 = __shfl_down_sync(0xFFFFFFFFu, p1, 1);
            float rp2 = __shfl_down_sync(0xFFFFFFFFu, p2, 1);
            float rp3 = __shfl_down_sync(0xFFFFFFFFu, p3, 1);

            // warp-edge fixups from gmem halos (hl/hr = -inf when absent)
            const float hs3 = hl.w;
            const float hs2 = fmaxf(hl.z, hs3);
            const float hs1 = fmaxf(hl.y, hs2);
            const float hs0 = fmaxf(hl.x, hs1);
            ls0 = (lane == 0) ? hs0 : ls0;
            ls1 = (lane == 0) ? hs1 : ls1;
            ls2 = (lane == 0) ? hs2 : ls2;
            ls3 = (lane == 0) ? hs3 : ls3;
            const float hp0 = hr.x;
            const float hp1 = fmaxf(hp0, hr.y);
            const float hp2 = fmaxf(hp1, hr.z);
            const float hp3 = fmaxf(hp2, hr.w);
            rp0 = (lane == 31) ? hp0 : rp0;
            rp1 = (lane == 31) ? hp1 : rp1;
            rp2 = (lane == 31) ? hp2 : rp2;
            rp3 = (lane == 31) ? hp3 : rp3;

            // horizontal 9-max
            float4 hm;
            hm.x = fmaxf(fmaxf(ls0, rp0), p3);
            hm.y = fmaxf(fmaxf(ls1, rp1), p3);
            hm.z = fmaxf(fmaxf(ls2, rp2), p3);
            hm.w = fmaxf(fmaxf(ls3, rp3), p3);

            // vertical sliding 9-max: pair/quad/oct chain, 4 f4max per row
            const float4 hprev = hmr[(u + 1) & 1];
            hmr[u & 1] = hm;
            pr[u & 3] = f4max(hm, hprev);                 // rows {r-1, r}
            qd[u & 7] = f4max(pr[u & 3], pr[(u + 2) & 3]);  // {r-3..r}
            oc[u & 1] = f4max(qd[u & 7], qd[(u + 4) & 7]);  // {r-7..r}

            if (it > 0) {
                const float4 win = f4max(oc[u & 1], oc[(u + 1) & 1]); // {r-8..r}
                const int j = r - 4;                       // center row
                if (active) {
                    const float4 vc = vr[(u + 4) & 7];     // x at row j
                    const float4 dv = __ldg(d4 + j * GW + gx);
                    const int obase = (b * Hn + j) * Wn + gx * 4;
                    if (vc.x == dv.x && win.x <= vc.x) atomicAdd(out + obase + 0, vc.x);
                    if (vc.y == dv.y && win.y <= vc.y) atomicAdd(out + obase + 1, vc.y);
                    if (vc.z == dv.z && win.z <= vc.z) atomicAdd(out + obase + 2, vc.z);
                    if (vc.w == dv.w && win.w <= vc.w) atomicAdd(out + obase + 3, vc.w);
                }
            }
        }
    }
}

extern "C" void kernel_launch(void* const* d_in, const int* in_sizes, int n_in,
                              void* d_out, int out_size) {
    const float* x = (const float*)d_in[0];
    float* out = (float*)d_out;
    (void)in_sizes; (void)n_in; (void)out_size;

    dim3 gA((Bn * HW4) / 256, 4);
    dmax_partial_kernel<<<gA, 256>>>(x);               // 250x4 blocks
    dmax_merge_kernel<<<(Bn * HW4) / 256, 256>>>(out); // 250 blocks
    sweep_kernel<<<Bn * Cn, LANES>>>(x, out);          // 1024 blocks
}